// round 13
// baseline (speedup 1.0000x reference)
#include <cuda_runtime.h>
#include <cuda_fp16.h>
#include <cstdint>

#define N_ROWS 8192
#define D      256
#define K      8192
#define DEPTH  4
#define CB_STRIDE ((K + 1) * D)
#define LOSS_SCALE (0.25f / (4.0f * 2097152.0f))
#define MARGIN 8e-3f
#define FLT_BIG 3.402823466e38f

#define BM 128
#define BN 256
#define ATILE 16384                  // 128 rows x 128B per k-chunk
#define BTILE 32768                  // 256 rows x 128B per k-chunk
#define SM_B  (4 * ATILE)            // A resident: 65536
#define SMEMT (SM_B + 3 * BTILE)     // 163840 -> 1 CTA/SM

// ---------------- persistent scratch ----------------
__device__ __align__(256) float  g_res[N_ROWS * D];
__device__ __align__(256) float  g_agg[N_ROWS * D];
__device__ __align__(256) __half g_res_h[N_ROWS * D];
__device__ __align__(256) __half g_cb_h[DEPTH * K * D];
__device__ __align__(16)  float  g_cc[DEPTH * K];
__device__ __align__(16)  unsigned long long g_top[N_ROWS * 64];   // 32 tiles x top-2

// ---------------- helpers ----------------
__device__ __forceinline__ uint32_t smem_u32(const void* p) {
    uint32_t a;
    asm("{ .reg .u64 t; cvta.to.shared.u64 t, %1; cvt.u32.u64 %0, t; }" : "=r"(a) : "l"(p));
    return a;
}
__device__ __forceinline__ uint32_t swz(uint32_t x) { return x ^ ((x >> 3) & 0x70u); }
__device__ __forceinline__ uint32_t h2_as_u32(__half2 h) {
    return *reinterpret_cast<uint32_t*>(&h);
}
__device__ __forceinline__ unsigned int f2ord(float f) {
    unsigned int u = __float_as_uint(f);
    return (u & 0x80000000u) ? ~u : (u | 0x80000000u);
}
__device__ __forceinline__ float ord2f(unsigned int o) {
    unsigned int u = (o & 0x80000000u) ? (o & 0x7FFFFFFFu) : ~o;
    return __uint_as_float(u);
}
__device__ __forceinline__ void merge2(unsigned long long& b1, unsigned long long& b2,
                                       unsigned long long o1, unsigned long long o2) {
    if (o1 < b1) { b2 = (b1 < o2) ? b1 : o2; b1 = o1; }
    else if (o1 < b2) { b2 = o1; }
}
__device__ __forceinline__ void push2(unsigned long long& b1, unsigned long long& b2,
                                      unsigned long long k) {
    if (k < b1) { b2 = b1; b1 = k; }
    else if (k < b2) { b2 = k; }
}

__device__ __forceinline__ void cpa16(uint32_t dst, const void* src) {
    asm volatile("cp.async.cg.shared.global [%0], [%1], 16;" :: "r"(dst), "l"(src));
}
#define CP_COMMIT() asm volatile("cp.async.commit_group;" ::: "memory")
#define CP_WAIT(n)  asm volatile("cp.async.wait_group %0;" :: "n"(n) : "memory")

#define LDSM4(r0, r1, r2, r3, a) \
    asm volatile("ldmatrix.sync.aligned.m8n8.x4.shared.b16 {%0,%1,%2,%3}, [%4];" \
                 : "=r"(r0), "=r"(r1), "=r"(r2), "=r"(r3) : "r"(a))

#define MMA16816(c, a, b0, b1) \
    asm volatile("mma.sync.aligned.m16n8k16.row.col.f32.f16.f16.f32 " \
                 "{%0,%1,%2,%3},{%4,%5,%6,%7},{%8,%9},{%0,%1,%2,%3};" \
                 : "+f"((c)[0]), "+f"((c)[1]), "+f"((c)[2]), "+f"((c)[3]) \
                 : "r"((a)[0]), "r"((a)[1]), "r"((a)[2]), "r"((a)[3]), "r"(b0), "r"(b1))

// reduce two values across a 256-thread block; result in thread 0
__device__ __forceinline__ void blockReduce2_256(float& a, float& b) {
    __shared__ float sa[8], sb2[8];
    int lane = threadIdx.x & 31, w = threadIdx.x >> 5;
#pragma unroll
    for (int o = 16; o > 0; o >>= 1) {
        a += __shfl_down_sync(0xffffffffu, a, o);
        b += __shfl_down_sync(0xffffffffu, b, o);
    }
    if (lane == 0) { sa[w] = a; sb2[w] = b; }
    __syncthreads();
    if (w == 0) {
        a = (lane < 8) ? sa[lane] : 0.f;
        b = (lane < 8) ? sb2[lane] : 0.f;
#pragma unroll
        for (int o = 4; o > 0; o >>= 1) {
            a += __shfl_down_sync(0xffu, a, o);
            b += __shfl_down_sync(0xffu, b, o);
        }
    }
}

// ---------------- setup ----------------
__global__ void k_init(const float* __restrict__ x) {
    int i = blockIdx.x * blockDim.x + threadIdx.x;
    if (i < N_ROWS * D) {
        float v = x[i];
        g_res[i] = v; g_agg[i] = 0.f;
        g_res_h[i] = __float2half_rn(v);
    }
}

__global__ void k_cb(const float* __restrict__ cbs) {
    int rid = blockIdx.x;                     // 0 .. DEPTH*K-1
    int dd = rid / K, r = rid % K;
    float v = cbs[(size_t)dd * CB_STRIDE + (size_t)r * D + threadIdx.x];
    g_cb_h[(size_t)rid * D + threadIdx.x] = __float2half_rn(v);
    float a = v * v, b = 0.f;
    blockReduce2_256(a, b);
    if (threadIdx.x == 0) g_cc[rid] = a;
}

__global__ void k_zero(float* __restrict__ loss) {
    if (threadIdx.x == 0) *loss = 0.f;
}

// load one ks-step's A+B fragments for a 64x64 warp tile
__device__ __forceinline__ void load_frags(uint32_t aT, uint32_t bT,
                                           uint32_t aLin, uint32_t bLin, int ks,
                                           uint32_t Af[4][4], uint32_t Bf[4][4]) {
#pragma unroll
    for (int ma = 0; ma < 4; ma++)
        LDSM4(Af[ma][0], Af[ma][1], Af[ma][2], Af[ma][3],
              aT + swz(aLin + ma * 2048 + ks * 32));
#pragma unroll
    for (int nb = 0; nb < 4; nb++)
        LDSM4(Bf[nb][0], Bf[nb][1], Bf[nb][2], Bf[nb][3],
              bT + swz(bLin + nb * 2048 + ks * 32));
}

__device__ __forceinline__ void do_mma(float acc[4][8][4],
                                       uint32_t Af[4][4], uint32_t Bf[4][4]) {
#pragma unroll
    for (int ma = 0; ma < 4; ma++)
#pragma unroll
        for (int nbq = 0; nbq < 4; nbq++) {
            MMA16816(acc[ma][2 * nbq + 0], Af[ma], Bf[nbq][0], Bf[nbq][1]);
            MMA16816(acc[ma][2 * nbq + 1], Af[ma], Bf[nbq][2], Bf[nbq][3]);
        }
}

// ---------------- HMMA GEMM: 1 CTA/SM, 64x64 warp tiles, frag double-buffer ---
// grid = (64, 32), block = 256 (8 warps: 2 row x 4 col)
__global__ void __launch_bounds__(256, 1) k_gemm(int dep) {
    extern __shared__ char smem[];
    const uint32_t sb = smem_u32(smem);
    const int tid = threadIdx.x, lane = tid & 31, wid = tid >> 5;
    const int wm = wid & 1, wn = wid >> 1;
    const int rowBase = blockIdx.x * BM, candBase = blockIdx.y * BN;

    const char* Ag = (const char*)(g_res_h + (size_t)rowBase * D);
    const char* Bg = (const char*)(g_cb_h + ((size_t)dep * K + (size_t)candBase) * D);

    const int r0 = tid >> 3, j0 = tid & 7;
    uint32_t sdst[8];
#pragma unroll
    for (int i = 0; i < 8; i++) sdst[i] = swz((uint32_t)(r0 + i * 32) * 128u + j0 * 16u);
    const uint32_t gOff = (uint32_t)r0 * 512u + (uint32_t)j0 * 16u;

    float acc[4][8][4];
#pragma unroll
    for (int a = 0; a < 4; a++)
#pragma unroll
        for (int b = 0; b < 8; b++)
#pragma unroll
            for (int q = 0; q < 4; q++) acc[a][b][q] = 0.f;

    const uint32_t aLin = (uint32_t)((wm * 64 + (lane & 15)) * 128 + (lane >> 4) * 16);
    const uint32_t bLin = (uint32_t)((wn * 64 + (lane & 7) + ((lane >> 4) << 3)) * 128 +
                                     ((lane >> 3) & 1) * 16);

    // prologue: G0 = A(all 4 chunks) + B0;  G1 = B1;  G2 = B2
#pragma unroll
    for (int chA = 0; chA < 4; chA++)
#pragma unroll
        for (int i = 0; i < 4; i++)
            cpa16(sb + chA * ATILE + sdst[i],
                  Ag + gOff + i * 32u * 512u + (uint32_t)chA * 128u);
#pragma unroll
    for (int i = 0; i < 8; i++)
        cpa16(sb + SM_B + sdst[i], Bg + gOff + i * 32u * 512u);
    CP_COMMIT();
#pragma unroll
    for (int i = 0; i < 8; i++)
        cpa16(sb + SM_B + BTILE + sdst[i], Bg + gOff + i * 32u * 512u + 128u);
    CP_COMMIT();
#pragma unroll
    for (int i = 0; i < 8; i++)
        cpa16(sb + SM_B + 2 * BTILE + sdst[i], Bg + gOff + i * 32u * 512u + 256u);
    CP_COMMIT();

#pragma unroll
    for (int kc = 0; kc < 4; kc++) {
        if (kc <= 1) { CP_WAIT(2); }
        else if (kc == 2) { CP_WAIT(1); }
        else { CP_WAIT(0); }
        __syncthreads();

        const uint32_t aT = sb + (uint32_t)kc * ATILE;
        const uint32_t bT = sb + SM_B + (uint32_t)(kc == 3 ? 0 : kc) * BTILE;

        uint32_t Af[2][4][4], Bf[2][4][4];
        load_frags(aT, bT, aLin, bLin, 0, Af[0], Bf[0]);
#pragma unroll
        for (int ks = 0; ks < 4; ks++) {
            if (ks < 3)
                load_frags(aT, bT, aLin, bLin, ks + 1, Af[(ks + 1) & 1], Bf[(ks + 1) & 1]);
            do_mma(acc, Af[ks & 1], Bf[ks & 1]);
        }

        if (kc == 0) {
            __syncthreads();            // all warps done reading B stage 0
#pragma unroll
            for (int i = 0; i < 8; i++) // prefetch B3 into stage 0
                cpa16(sb + SM_B + sdst[i], Bg + gOff + i * 32u * 512u + 384u);
            CP_COMMIT();
        }
    }

    // ---- epilogue: per-row top-2 over this CTA's 256 cols ----
    __syncthreads();                    // A tile reads done; alias sTop
    unsigned long long* sTop = (unsigned long long*)smem;   // [128 rows][4 wn][2]
    const float* cc = g_cc + (size_t)dep * K;
    const int colBase = candBase + wn * 64 + (lane & 3) * 2;

    float2 ccv[8];
#pragma unroll
    for (int g = 0; g < 8; g++) ccv[g] = *(const float2*)&cc[colBase + g * 8];

#pragma unroll
    for (int ma = 0; ma < 4; ma++) {
#pragma unroll
        for (int rb = 0; rb < 2; rb++) {
            float d1 = FLT_BIG, d2 = FLT_BIG;
            int i1 = 0, i2 = 0;
#pragma unroll
            for (int g = 0; g < 8; g++) {
                const int col = colBase + g * 8;
                float k0 = fmaf(-2.f, acc[ma][g][rb * 2 + 0], ccv[g].x);
                float k1 = fmaf(-2.f, acc[ma][g][rb * 2 + 1], ccv[g].y);
                if (k0 < d2) {
                    if (k0 < d1) { d2 = d1; i2 = i1; d1 = k0; i1 = col; }
                    else { d2 = k0; i2 = col; }
                }
                if (k1 < d2) {
                    if (k1 < d1) { d2 = d1; i2 = i1; d1 = k1; i1 = col + 1; }
                    else { d2 = k1; i2 = col + 1; }
                }
            }
            unsigned long long b1 =
                ((unsigned long long)f2ord(d1) << 32) | (unsigned int)i1;
            unsigned long long b2 =
                ((unsigned long long)f2ord(d2) << 32) | (unsigned int)i2;
#pragma unroll
            for (int off = 1; off <= 2; off <<= 1) {
                unsigned long long o1 = __shfl_xor_sync(0xffffffffu, b1, off);
                unsigned long long o2 = __shfl_xor_sync(0xffffffffu, b2, off);
                merge2(b1, b2, o1, o2);
            }
            if ((lane & 3) == 0) {
                int rl = wm * 64 + ma * 16 + rb * 8 + (lane >> 2);
                sTop[(rl * 4 + wn) * 2 + 0] = b1;
                sTop[(rl * 4 + wn) * 2 + 1] = b2;
            }
        }
    }
    __syncthreads();
    if (tid < 128) {
        unsigned long long p1 = sTop[tid * 8 + 0];
        unsigned long long p2 = sTop[tid * 8 + 1];
#pragma unroll
        for (int j = 1; j < 4; j++)
            merge2(p1, p2, sTop[tid * 8 + j * 2], sTop[tid * 8 + j * 2 + 1]);
        size_t go = (size_t)(rowBase + tid) * 64 + blockIdx.y * 2;
        g_top[go + 0] = p1;
        g_top[go + 1] = p2;
    }
}

// ---------------- fused select + rescore + update: warp per row ----------------
// grid = N_ROWS/8 = 1024, block = 256 (8 warps)
__global__ void __launch_bounds__(256) k_finish(
        const float* __restrict__ x, const float* __restrict__ cb,
        float* __restrict__ out, float* __restrict__ codes,
        float* __restrict__ loss, int dep) {
    const int w = threadIdx.x >> 5, lane = threadIdx.x & 31;
    const int row = blockIdx.x * 8 + w;
    __shared__ unsigned long long se[8][64];
    __shared__ int sql[8][64];
    __shared__ float wloss[8];

    const unsigned long long* gt = g_top + (size_t)row * 64;
    unsigned long long b1 = ~0ull, b2 = ~0ull;
#pragma unroll
    for (int i = 0; i < 2; i++) {
        unsigned long long e = gt[lane + i * 32];
        se[w][lane + i * 32] = e;
        push2(b1, b2, e);
    }
#pragma unroll
    for (int off = 16; off > 0; off >>= 1) {
        unsigned long long o1 = __shfl_xor_sync(0xffffffffu, b1, off);
        unsigned long long o2 = __shfl_xor_sync(0xffffffffu, b2, off);
        merge2(b1, b2, o1, o2);
    }
    float d1 = ord2f((unsigned int)(b1 >> 32));
    float d2 = ord2f((unsigned int)(b2 >> 32));
    int idx = (int)(b1 & 0xFFFFFFFFu);

    const float4* rr = (const float4*)(g_res + (size_t)row * D);
    float4 r0 = rr[lane * 2], r1 = rr[lane * 2 + 1];

    if (d2 - d1 < MARGIN) {
        const float thr = d1 + MARGIN;
        int nq = 0;
        __syncwarp();
#pragma unroll
        for (int i = 0; i < 2; i++) {
            unsigned long long e = se[w][lane + i * 32];
            bool qf = ord2f((unsigned int)(e >> 32)) <= thr;
            unsigned m = __ballot_sync(0xffffffffu, qf);
            if (qf) {
                int pos = nq + __popc(m & ((1u << lane) - 1u));
                sql[w][pos] = (int)(e & 0xFFFFFFFFu);
            }
            nq += __popc(m);
        }
        __syncwarp();
        unsigned long long best = ~0ull;
        const float* ccd = g_cc + (size_t)dep * K;
        for (int q = 0; q < nq; q++) {
            int cand = sql[w][q];
            const float4* cr = (const float4*)(cb + (size_t)cand * D);
            float4 c0 = cr[lane * 2], c1 = cr[lane * 2 + 1];
            float p = r0.x * c0.x + r0.y * c0.y + r0.z * c0.z + r0.w * c0.w
                    + r1.x * c1.x + r1.y * c1.y + r1.z * c1.z + r1.w * c1.w;
#pragma unroll
            for (int o = 16; o > 0; o >>= 1) p += __shfl_xor_sync(0xffffffffu, p, o);
            float dist = ccd[cand] - 2.f * p;
            unsigned long long key =
                ((unsigned long long)f2ord(dist) << 32) | (unsigned int)cand;
            if (key < best) best = key;
        }
        idx = (int)(best & 0xFFFFFFFFu);
    }

    const size_t o4 = (size_t)row * (D / 4) + lane * 2;
    const float4* cbv = (const float4*)(cb + (size_t)idx * D);
    float4 q0 = cbv[lane * 2], q1 = cbv[lane * 2 + 1];
    float4 a0 = ((const float4*)g_agg)[o4], a1 = ((const float4*)g_agg)[o4 + 1];
    a0.x += q0.x; a0.y += q0.y; a0.z += q0.z; a0.w += q0.w;
    a1.x += q1.x; a1.y += q1.y; a1.z += q1.z; a1.w += q1.w;
    float4 x0 = ((const float4*)x)[o4], x1 = ((const float4*)x)[o4 + 1];

    if (dep < DEPTH - 1) {
        float4 n0, n1;
        n0.x = r0.x - q0.x; n0.y = r0.y - q0.y; n0.z = r0.z - q0.z; n0.w = r0.w - q0.w;
        n1.x = r1.x - q1.x; n1.y = r1.y - q1.y; n1.z = r1.z - q1.z; n1.w = r1.w - q1.w;
        ((float4*)g_res)[o4] = n0;
        ((float4*)g_res)[o4 + 1] = n1;
        uint4 hh;
        hh.x = h2_as_u32(__float22half2_rn(make_float2(n0.x, n0.y)));
        hh.y = h2_as_u32(__float22half2_rn(make_float2(n0.z, n0.w)));
        hh.z = h2_as_u32(__float22half2_rn(make_float2(n1.x, n1.y)));
        hh.w = h2_as_u32(__float22half2_rn(make_float2(n1.z, n1.w)));
        *(uint4*)(g_res_h + (size_t)row * D + lane * 8) = hh;
        ((float4*)g_agg)[o4] = a0;
        ((float4*)g_agg)[o4 + 1] = a1;
    } else {
        float4 ov0, ov1;
        ov0.x = x0.x + (a0.x - x0.x); ov0.y = x0.y + (a0.y - x0.y);
        ov0.z = x0.z + (a0.z - x0.z); ov0.w = x0.w + (a0.w - x0.w);
        ov1.x = x1.x + (a1.x - x1.x); ov1.y = x1.y + (a1.y - x1.y);
        ov1.z = x1.z + (a1.z - x1.z); ov1.w = x1.w + (a1.w - x1.w);
        ((float4*)out)[o4] = ov0;
        ((float4*)out)[o4 + 1] = ov1;
    }

    float d0x = x0.x - a0.x, d0y = x0.y - a0.y, d0z = x0.z - a0.z, d0w = x0.w - a0.w;
    float d1x = x1.x - a1.x, d1y = x1.y - a1.y, d1z = x1.z - a1.z, d1w = x1.w - a1.w;
    float s2 = d0x * d0x + d0y * d0y + d0z * d0z + d0w * d0w
             + d1x * d1x + d1y * d1y + d1z * d1z + d1w * d1w;
#pragma unroll
    for (int o = 16; o > 0; o >>= 1) s2 += __shfl_down_sync(0xffffffffu, s2, o);
    if (lane == 0) {
        wloss[w] = s2;
        codes[(size_t)row * DEPTH + dep] = (float)idx;
    }
    __syncthreads();
    if (threadIdx.x == 0) {
        float t = 0.f;
#pragma unroll
        for (int i = 0; i < 8; i++) t += wloss[i];
        atomicAdd(loss, t * LOSS_SCALE);
    }
}

extern "C" void kernel_launch(void* const* d_in, const int* in_sizes, int n_in,
                              void* d_out, int out_size) {
    const float* x = (const float*)d_in[0];
    const float* cbs = (const float*)d_in[1];
    float* out = (float*)d_out;
    float* loss = out + (size_t)N_ROWS * D;
    float* codes = loss + 1;

    cudaFuncSetAttribute(k_gemm, cudaFuncAttributeMaxDynamicSharedMemorySize, SMEMT);

    k_init<<<(N_ROWS * D + 255) / 256, 256>>>(x);         // launch 0
    k_cb<<<DEPTH * K, 256>>>(cbs);                        // launch 1
    k_zero<<<1, 32>>>(loss);                              // launch 2

    for (int d = 0; d < DEPTH; d++) {
        const float* cb = cbs + (size_t)d * CB_STRIDE;
        dim3 grid(N_ROWS / BM, K / BN);
        k_gemm<<<grid, 256, SMEMT>>>(d);                  // launches 3,5,7,9
        k_finish<<<N_ROWS / 8, 256>>>(x, cb, out, codes, loss, d);
    }
}